// round 9
// baseline (speedup 1.0000x reference)
#include <cuda_runtime.h>
#include <cuda.h>
#include <cuda_bf16.h>
#include <cstdint>

// ============================================================================
// y[8192,4096] = x @ Wq^T + b,  Wq = per-tensor int8 dequant of W.
// w_int exact in bf16; x split hi+lo bf16; two accumulated bf16 tcgen05 GEMMs
// into one fp32 TMEM accumulator; epilogue y = scale*acc + b.
//
// R9: 4-CTA cluster (2m x 2n) with TMA multicast of A (across n-siblings) and
// B (across m-siblings): GEMM L2 traffic 4GB -> 1.5GB, GEMM becomes
// tensor-floor-bound (~250us). Empty barriers count=4 + multicast tcgen05
// commit make producer overwrite of sibling SMEM safe.
//
// tcgen05/TMA-multicast PTX is arch-'a'-gated so the harness's compute_103
// (non-'a') pass compiles a stub; runtime probe + always-compiled fallback
// keep the answer correct under either loaded image.
// ============================================================================

#if defined(__CUDA_ARCH_FEAT_SM103_ALL) || defined(__CUDA_ARCH_FEAT_SM100_ALL) || \
    defined(__CUDA_ARCH_FEAT_SM101_ALL)
#define HAS_TCGEN05 1
#else
#define HAS_TCGEN05 0
#endif

static constexpr int Mdim = 8192, Ndim = 4096, Kdim = 4096;
static constexpr int MT = 128, NT = 512, KC = 64;         // tile sizes
static constexpr int NCHUNK = Kdim / KC;                  // 64
static constexpr int STAGES = 2;
static constexpr int A_BYTES = MT * 128;                  // 16384 (128B rows)
static constexpr int B_BYTES = NT * 128;                  // 65536
static constexpr int STAGE_BYTES = 2 * A_BYTES + B_BYTES; // 98304
static constexpr int OFF_AHI = 1024;
static constexpr int OFF_ALO = OFF_AHI + A_BYTES;         // 17408
static constexpr int OFF_B   = OFF_ALO + A_BYTES;         // 33792
static constexpr int SMEM_TOTAL = 1024 + STAGES * STAGE_BYTES; // 197632
static constexpr int CLUSTER = 4;                         // 2m x 2n

// idesc kind::f16: dtype=F32, atype=BF16, btype=BF16, N=256, M=128
static constexpr uint32_t IDESC =
    (1u << 4) | (1u << 7) | (1u << 10) | ((256u / 8) << 17) | ((128u / 16) << 24);

// ---------------- persistent scratch (no cudaMalloc allowed) ----------------
__device__ __align__(16) __nv_bfloat16 g_W8 [(size_t)Ndim * Kdim]; // 32MB
__device__ __align__(16) __nv_bfloat16 g_Xhi[(size_t)Mdim * Kdim]; // 64MB
__device__ __align__(16) __nv_bfloat16 g_Xlo[(size_t)Mdim * Kdim]; // 64MB
__device__ float    g_scale;
__device__ unsigned g_absmax;
__device__ int      g_use_tc;

// ---------------- PTX helpers ----------------
__device__ __forceinline__ uint32_t smem_to_u32(const void* p) {
    uint32_t a;
    asm("{ .reg .u64 t; cvta.to.shared.u64 t, %1; cvt.u32.u64 %0, t; }"
        : "=r"(a) : "l"(p));
    return a;
}

__device__ __forceinline__ uint32_t elect_one_pred() {
    uint32_t pred;
    asm volatile(
        "{\n\t.reg .pred p;\n\telect.sync _|p, 0xFFFFFFFF;\n\tselp.b32 %0, 1, 0, p;\n\t}"
        : "=r"(pred));
    return pred;
}

__device__ __forceinline__ uint32_t cluster_rank() {
    uint32_t r;
    asm("mov.u32 %0, %%cluster_ctarank;" : "=r"(r));
    return r;
}

#define CLUSTER_SYNC() do { \
    asm volatile("barrier.cluster.arrive.aligned;" ::: "memory"); \
    asm volatile("barrier.cluster.wait.aligned;"   ::: "memory"); \
} while (0)

#define MBARRIER_INIT(addr, cnt) \
    asm volatile("mbarrier.init.shared.b64 [%0], %1;" :: "r"((uint32_t)(addr)), "r"((uint32_t)(cnt)) : "memory")

#define MBARRIER_EXPECT_TX(addr, bytes) \
    asm volatile("mbarrier.arrive.expect_tx.shared.b64 _, [%0], %1;" :: "r"((uint32_t)(addr)), "r"((uint32_t)(bytes)) : "memory")

#define MBARRIER_WAIT_PARITY(addr, par) do { \
    uint32_t _m = (uint32_t)(addr), _p = (uint32_t)(par), _d; \
    asm volatile("{\n\t.reg .pred p;\n\tmbarrier.try_wait.parity.acquire.cta.shared::cta.b64 p, [%1], %2;\n\tselp.b32 %0, 1, 0, p;\n\t}" \
        : "=r"(_d) : "r"(_m), "r"(_p) : "memory"); \
    if (!_d) { \
        asm volatile("{\n\t.reg .pred P1;\n\tWL_%=:\n\tmbarrier.try_wait.parity.acquire.cta.shared::cta.b64 P1, [%0], %1, 0x989680;\n\t@P1 bra.uni WD_%=;\n\tbra.uni WL_%=;\n\tWD_%=:\n\t}" \
            :: "r"(_m), "r"(_p) : "memory"); \
    } \
} while (0)

#define MBARRIER_WAIT_PARITY_RELAXED(addr, par) do { \
    uint32_t _m = (uint32_t)(addr), _p = (uint32_t)(par), _d; \
    asm volatile("{\n\t.reg .pred p;\n\tmbarrier.try_wait.parity.relaxed.cta.shared::cta.b64 p, [%1], %2, 0x989680;\n\tselp.b32 %0, 1, 0, p;\n\t}" \
        : "=r"(_d) : "r"(_m), "r"(_p) : "memory"); \
    if (!_d) { \
        asm volatile("{\n\t.reg .pred P1;\n\tWL_%=:\n\tmbarrier.try_wait.parity.relaxed.cta.shared::cta.b64 P1, [%0], %1, 0x989680;\n\t@P1 bra.uni WD_%=;\n\tbra.uni WL_%=;\n\tWD_%=:\n\t}" \
            :: "r"(_m), "r"(_p) : "memory"); \
    } \
} while (0)

#define TCGEN05_ALLOC(smem_addr, n) \
    asm volatile("tcgen05.alloc.cta_group::1.sync.aligned.shared::cta.b32 [%0], %1;" \
        :: "r"((uint32_t)(smem_addr)), "r"((uint32_t)(n)) : "memory")

#define TCGEN05_DEALLOC(tmem, n) \
    asm volatile("tcgen05.dealloc.cta_group::1.sync.aligned.b32 %0, %1;" :: "r"(tmem), "r"((uint32_t)(n)))

#define TCGEN05_RELINQUISH() \
    asm volatile("tcgen05.relinquish_alloc_permit.cta_group::1.sync.aligned;")

#define TCGEN05_COMMIT(mbar) \
    asm volatile("tcgen05.commit.cta_group::1.mbarrier::arrive::one.shared::cluster.b64 [%0];" \
        :: "r"((uint32_t)(mbar)) : "memory")

// multicast commit: on MMA drain, arrive on empty barrier at same SMEM offset
// in every cluster CTA in mask (makes sibling-buffer overwrite safe).
#define TCGEN05_COMMIT_MC(mbar, mask) \
    asm volatile("tcgen05.commit.cta_group::1.mbarrier::arrive::one.shared::cluster.multicast::cluster.b64 [%0], %1;" \
        :: "r"((uint32_t)(mbar)), "h"((uint16_t)(mask)) : "memory")

#define TCGEN05_FENCE_AFTER() asm volatile("tcgen05.fence::after_thread_sync;" ::: "memory")
#define TCGEN05_WAIT_LD()     asm volatile("tcgen05.wait::ld.sync.aligned;" ::: "memory")

#define TCGEN05_LD_32X32B_X32(r, addr) \
    asm volatile("tcgen05.ld.sync.aligned.32x32b.x32.b32 " \
        "{%0, %1, %2, %3, %4, %5, %6, %7, %8, %9, %10, %11, %12, %13, %14, %15, " \
        " %16, %17, %18, %19, %20, %21, %22, %23, %24, %25, %26, %27, %28, %29, %30, %31}, [%32];" \
        : "=r"((r)[0]),  "=r"((r)[1]),  "=r"((r)[2]),  "=r"((r)[3]), \
          "=r"((r)[4]),  "=r"((r)[5]),  "=r"((r)[6]),  "=r"((r)[7]), \
          "=r"((r)[8]),  "=r"((r)[9]),  "=r"((r)[10]), "=r"((r)[11]), \
          "=r"((r)[12]), "=r"((r)[13]), "=r"((r)[14]), "=r"((r)[15]), \
          "=r"((r)[16]), "=r"((r)[17]), "=r"((r)[18]), "=r"((r)[19]), \
          "=r"((r)[20]), "=r"((r)[21]), "=r"((r)[22]), "=r"((r)[23]), \
          "=r"((r)[24]), "=r"((r)[25]), "=r"((r)[26]), "=r"((r)[27]), \
          "=r"((r)[28]), "=r"((r)[29]), "=r"((r)[30]), "=r"((r)[31]) \
        : "r"(addr))

// multicast TMA: deliver tile + complete_tx to same SMEM offset in every CTA in mask
#define TMA_LOAD_2D_MC(smem, map, cx, cy, mbar, mask) \
    asm volatile("cp.async.bulk.tensor.2d.shared::cluster.global.tile.mbarrier::complete_tx::bytes.multicast::cluster " \
        "[%0], [%1, {%2, %3}], [%4], %5;" \
        :: "r"((uint32_t)(smem)), "l"(map), "r"((int32_t)(cx)), "r"((int32_t)(cy)), \
           "r"((uint32_t)(mbar)), "h"((uint16_t)(mask)) : "memory")

// SW128 K-major SMEM descriptor (Blackwell): layout=SW128, version=1, SBO=64, LBO=1
static constexpr uint64_t SMEM_DESC_BASE_SW128 =
    (uint64_t(2) << 61) | (uint64_t(1) << 46) | (uint64_t(64) << 32) | (uint64_t(1) << 16);
#define MAKE_SMEM_DESC(a) (SMEM_DESC_BASE_SW128 | ((uint64_t)((a) >> 4) & 0x3FFF))

#if HAS_TCGEN05
// SS bf16 MMA, cta_group::1, fp32 accum (disable-lane vector = 4 zero regs)
__device__ __forceinline__ void mma_ss_f16(uint32_t d, uint64_t ad, uint64_t bd,
                                           uint32_t idesc, bool acc) {
    uint32_t en = acc ? 1u : 0u;
    asm volatile(
        "{\n\t.reg .pred p;\n\tsetp.ne.u32 p, %4, 0;\n\t"
        "tcgen05.mma.cta_group::1.kind::f16 [%0], %1, %2, %3, {%5, %5, %5, %5}, p;\n\t}"
        :: "r"(d), "l"(ad), "l"(bd), "r"(idesc), "r"(en), "r"(0u) : "memory");
}
#endif

// ---------------- prep kernels (arch-neutral) ----------------
__global__ void k_init() { g_absmax = 0u; g_use_tc = HAS_TCGEN05; }

__global__ void k_absmax(const float4* __restrict__ W4, int n4) {
    unsigned m = 0u;
    int stride = gridDim.x * blockDim.x;
    for (int i = blockIdx.x * blockDim.x + threadIdx.x; i < n4; i += stride) {
        float4 v = W4[i];
        m = max(m, __float_as_uint(fabsf(v.x)));
        m = max(m, __float_as_uint(fabsf(v.y)));
        m = max(m, __float_as_uint(fabsf(v.z)));
        m = max(m, __float_as_uint(fabsf(v.w)));
    }
    #pragma unroll
    for (int o = 16; o; o >>= 1) m = max(m, __shfl_xor_sync(0xffffffffu, m, o));
    __shared__ unsigned sm[8];
    if ((threadIdx.x & 31) == 0) sm[threadIdx.x >> 5] = m;
    __syncthreads();
    if (threadIdx.x == 0) {
        unsigned v = sm[0];
        #pragma unroll
        for (int w = 1; w < 8; w++) v = max(v, sm[w]);
        atomicMax(&g_absmax, v);
    }
}

union Pack4 { __nv_bfloat16 h[4]; uint2 u; };

__global__ void k_quant(const float4* __restrict__ W4, int n4) {
    float scale = __fdiv_rn(__uint_as_float(g_absmax), 127.0f);
    if (blockIdx.x == 0 && threadIdx.x == 0) g_scale = scale;
    float inv = __frcp_rn(scale);   // rcp then correct: use division for exactness
    (void)inv;
    int stride = gridDim.x * blockDim.x;
    for (int i = blockIdx.x * blockDim.x + threadIdx.x; i < n4; i += stride) {
        float4 v = W4[i];
        Pack4 p;
        p.h[0] = __float2bfloat16_rn(fminf(127.f, fmaxf(-127.f, rintf(__fdiv_rn(v.x, scale)))));
        p.h[1] = __float2bfloat16_rn(fminf(127.f, fmaxf(-127.f, rintf(__fdiv_rn(v.y, scale)))));
        p.h[2] = __float2bfloat16_rn(fminf(127.f, fmaxf(-127.f, rintf(__fdiv_rn(v.z, scale)))));
        p.h[3] = __float2bfloat16_rn(fminf(127.f, fmaxf(-127.f, rintf(__fdiv_rn(v.w, scale)))));
        reinterpret_cast<uint2*>(g_W8)[i] = p.u;
    }
}

__global__ void k_split(const float4* __restrict__ X4, int n4) {
    int stride = gridDim.x * blockDim.x;
    for (int i = blockIdx.x * blockDim.x + threadIdx.x; i < n4; i += stride) {
        float4 v = X4[i];
        Pack4 ph, pl;
        ph.h[0] = __float2bfloat16_rn(v.x); pl.h[0] = __float2bfloat16_rn(v.x - __bfloat162float(ph.h[0]));
        ph.h[1] = __float2bfloat16_rn(v.y); pl.h[1] = __float2bfloat16_rn(v.y - __bfloat162float(ph.h[1]));
        ph.h[2] = __float2bfloat16_rn(v.z); pl.h[2] = __float2bfloat16_rn(v.z - __bfloat162float(ph.h[2]));
        ph.h[3] = __float2bfloat16_rn(v.w); pl.h[3] = __float2bfloat16_rn(v.w - __bfloat162float(ph.h[3]));
        reinterpret_cast<uint2*>(g_Xhi)[i] = ph.u;
        reinterpret_cast<uint2*>(g_Xlo)[i] = pl.u;
    }
}

// ---------------- tcgen05 GEMM kernel (4-CTA cluster, multicast fills) -----
// cluster rank r: mt_sub = r>>1, nt_sub = r&1. Cluster covers 256x1024 block.
// A multicast across n-siblings, B multicast across m-siblings.
// warp 1 = producer (TMA), warp 0 = MMA issuer, all 4 warps = epilogue.
__global__ void __launch_bounds__(128, 1) __cluster_dims__(CLUSTER, 1, 1)
gemm_kernel(
    const __grid_constant__ CUtensorMap tmAhi,
    const __grid_constant__ CUtensorMap tmAlo,
    const __grid_constant__ CUtensorMap tmB,
    const float* __restrict__ bias,
    float* __restrict__ out)
{
#if HAS_TCGEN05
    extern __shared__ char smem[];
    uint32_t sb  = smem_to_u32(smem);
    int tid = threadIdx.x, wid = tid >> 5, lid = tid & 31;

    uint32_t rank = cluster_rank();
    int mt_sub = rank >> 1, nt_sub = rank & 1;
    int cid  = blockIdx.x >> 2;           // 128 clusters
    int cg_n = cid & 3, cg_m = cid >> 2;  // n-fastest: 4 clusters share cg_m
    int mt = cg_m * 2 + mt_sub;           // [0,64)  x MT=128
    int nt = cg_n * 2 + nt_sub;           // [0,8)   x NT=512

    const uint32_t TMEMP = sb;
    const uint32_t FULLB = sb + 8;   // full[0]=+8, full[1]=+16
    const uint32_t EMPTB = sb + 24;  // empty[0]=+24, empty[1]=+32
    const uint32_t DONEB = sb + 40;

    if (wid == 0) TCGEN05_ALLOC(TMEMP, 512);
    if (tid == 0) {
        MBARRIER_INIT(FULLB, 1);         MBARRIER_INIT(FULLB + 8, 1);
        MBARRIER_INIT(EMPTB, CLUSTER);   MBARRIER_INIT(EMPTB + 8, CLUSTER);
        MBARRIER_INIT(DONEB, 1);
    }
    __syncthreads();
    uint32_t tmem;
    asm volatile("ld.shared.b32 %0, [%1];" : "=r"(tmem) : "r"(TMEMP));
    if (wid == 0) TCGEN05_RELINQUISH();

    // all cluster mbarriers must be live before any multicast targets them
    CLUSTER_SYNC();

    if (wid == 1) {
        if (elect_one_pred()) {
            const uint16_t amask = (uint16_t)(0x3u << (mt_sub * 2)); // n-siblings
            const uint16_t bmask = (uint16_t)(0x5u << nt_sub);       // m-siblings
            const bool loadA = (nt_sub == 0);
            const bool loadB = (mt_sub == 0);
            for (int i = 0; i < NCHUNK; i++) {
                int s = i & 1;
                uint32_t full = FULLB + s * 8;
                // empty flips when ALL 4 cluster CTAs' MMAs for stage s drained
                if (i >= STAGES)
                    MBARRIER_WAIT_PARITY_RELAXED(EMPTB + s * 8, ((i >> 1) - 1) & 1);
                MBARRIER_EXPECT_TX(full, STAGE_BYTES);
                int k0 = i * KC;
                uint32_t base = sb + s * STAGE_BYTES;
                if (loadA) {
                    TMA_LOAD_2D_MC(base + OFF_AHI, &tmAhi, k0, mt * MT, full, amask);
                    TMA_LOAD_2D_MC(base + OFF_ALO, &tmAlo, k0, mt * MT, full, amask);
                }
                if (loadB) {
                    TMA_LOAD_2D_MC(base + OFF_B,         &tmB, k0, nt * NT,       full, bmask);
                    TMA_LOAD_2D_MC(base + OFF_B + 32768, &tmB, k0, nt * NT + 256, full, bmask);
                }
            }
        }
    } else if (wid == 0) {
        if (elect_one_pred()) {
            uint64_t dAhi[2], dAlo[2], dB[2];
            #pragma unroll
            for (int s = 0; s < 2; s++) {
                dAhi[s] = MAKE_SMEM_DESC(sb + OFF_AHI + s * STAGE_BYTES);
                dAlo[s] = MAKE_SMEM_DESC(sb + OFF_ALO + s * STAGE_BYTES);
                dB[s]   = MAKE_SMEM_DESC(sb + OFF_B   + s * STAGE_BYTES);
            }
            for (int i = 0; i < NCHUNK; i++) {
                int s = i & 1;
                MBARRIER_WAIT_PARITY(FULLB + s * 8, (i >> 1) & 1);
                #pragma unroll
                for (int nh = 0; nh < 2; nh++) {
                    uint32_t d  = tmem + nh * 256;             // cols [0,256),[256,512)
                    uint64_t bd = dB[s] + (uint64_t)nh * 2048; // +32KB in 16B units
                    #pragma unroll
                    for (int ks = 0; ks < 4; ks++)             // hi half of x
                        mma_ss_f16(d, dAhi[s] + ks * 2, bd + ks * 2, IDESC, !(i == 0 && ks == 0));
                    #pragma unroll
                    for (int ks = 0; ks < 4; ks++)             // lo half of x
                        mma_ss_f16(d, dAlo[s] + ks * 2, bd + ks * 2, IDESC, true);
                }
                // arrive on empty[s] in ALL cluster CTAs (producers of this buffer)
                TCGEN05_COMMIT_MC(EMPTB + s * 8, 0xF);
            }
            TCGEN05_COMMIT(DONEB);  // in-order: fires after all local MMAs complete
        }
    }

    __syncthreads();
    MBARRIER_WAIT_PARITY(DONEB, 0);
    TCGEN05_FENCE_AFTER();

    // epilogue: each warp reads its 32-lane TMEM subpartition, 32 cols at a time
    float scale = g_scale;
    size_t m = (size_t)(mt * MT + wid * 32 + lid);
    float* orow = out + m * Ndim + (size_t)nt * NT;
    const float* brow = bias + nt * NT;
    for (int cb = 0; cb < NT; cb += 32) {
        uint32_t r[32];
        TCGEN05_LD_32X32B_X32(r, tmem + cb);
        TCGEN05_WAIT_LD();
        float y[32];
        #pragma unroll
        for (int j = 0; j < 32; j++)
            y[j] = fmaf(scale, __uint_as_float(r[j]), __ldg(brow + cb + j));
        #pragma unroll
        for (int j = 0; j < 32; j += 4)
            *reinterpret_cast<float4*>(orow + cb + j) =
                make_float4(y[j], y[j + 1], y[j + 2], y[j + 3]);
    }

    __syncthreads();
    if (wid == 0) TCGEN05_DEALLOC(tmem, 512);
    // no CTA may exit while sibling multicasts could still target its SMEM
    CLUSTER_SYNC();
#else
    (void)tmAhi; (void)tmAlo; (void)tmB; (void)bias; (void)out;
#endif
}

// ---------------- always-compiled fallback GEMM (runs only if stub image) ---
__global__ void __launch_bounds__(256) fallback_gemm(
    const float* __restrict__ x, const float* __restrict__ bias,
    float* __restrict__ out)
{
    if (g_use_tc) return;   // tcgen05 path already produced the result

    __shared__ float As[16][68];
    __shared__ float Bs[16][68];

    int tid = threadIdx.x;
    int tx = tid & 15, ty = tid >> 4;
    int n0 = blockIdx.x * 64, m0 = blockIdx.y * 64;
    float scale = g_scale;

    float acc[4][4];
    #pragma unroll
    for (int i = 0; i < 4; i++)
        #pragma unroll
        for (int j = 0; j < 4; j++) acc[i][j] = 0.f;

    int lrow = tid >> 2;
    int lk4  = (tid & 3) * 4;

    for (int k0 = 0; k0 < Kdim; k0 += 16) {
        float4 av = *reinterpret_cast<const float4*>(
            x + (size_t)(m0 + lrow) * Kdim + k0 + lk4);
        As[lk4 + 0][lrow] = av.x; As[lk4 + 1][lrow] = av.y;
        As[lk4 + 2][lrow] = av.z; As[lk4 + 3][lrow] = av.w;
        uint2 bu = *reinterpret_cast<const uint2*>(
            g_W8 + (size_t)(n0 + lrow) * Kdim + k0 + lk4);
        Pack4 bp; bp.u = bu;
        Bs[lk4 + 0][lrow] = __bfloat162float(bp.h[0]);
        Bs[lk4 + 1][lrow] = __bfloat162float(bp.h[1]);
        Bs[lk4 + 2][lrow] = __bfloat162float(bp.h[2]);
        Bs[lk4 + 3][lrow] = __bfloat162float(bp.h[3]);
        __syncthreads();

        #pragma unroll
        for (int k = 0; k < 16; k++) {
            float a[4], bb[4];
            #pragma unroll
            for (int i = 0; i < 4; i++) a[i]  = As[k][ty * 4 + i];
            #pragma unroll
            for (int j = 0; j < 4; j++) bb[j] = Bs[k][tx * 4 + j];
            #pragma unroll
            for (int i = 0; i < 4; i++)
                #pragma unroll
                for (int j = 0; j < 4; j++)
                    acc[i][j] = fmaf(a[i], bb[j], acc[i][j]);
        }
        __syncthreads();
    }

    #pragma unroll
    for (int i = 0; i < 4; i++) {
        size_t m = (size_t)(m0 + ty * 4 + i);
        #pragma unroll
        for (int j = 0; j < 4; j++) {
            int n = n0 + tx * 4 + j;
            out[m * Ndim + n] = fmaf(scale, acc[i][j], __ldg(bias + n));
        }
    }
}

// ---------------- host launch ----------------
typedef CUresult (*PFN_encodeTiled)(
    CUtensorMap*, CUtensorMapDataType, cuuint32_t, void*,
    const cuuint64_t*, const cuuint64_t*, const cuuint32_t*, const cuuint32_t*,
    CUtensorMapInterleave, CUtensorMapSwizzle, CUtensorMapL2promotion,
    CUtensorMapFloatOOBfill);

static void make_map2d(PFN_encodeTiled enc, CUtensorMap* tm, void* ptr,
                       uint64_t d0, uint64_t d1, uint32_t b0, uint32_t b1) {
    cuuint64_t dims[2]    = {d0, d1};
    cuuint64_t strides[1] = {d0 * 2};  // bf16, K-major contiguous
    cuuint32_t box[2]     = {b0, b1};
    cuuint32_t es[2]      = {1, 1};
    enc(tm, CU_TENSOR_MAP_DATA_TYPE_BFLOAT16, 2, ptr, dims, strides, box, es,
        CU_TENSOR_MAP_INTERLEAVE_NONE, CU_TENSOR_MAP_SWIZZLE_128B,
        CU_TENSOR_MAP_L2_PROMOTION_L2_128B, CU_TENSOR_MAP_FLOAT_OOB_FILL_NONE);
}

extern "C" void kernel_launch(void* const* d_in, const int* in_sizes, int n_in,
                              void* d_out, int out_size) {
    const float* x = (const float*)d_in[0];   // [8192, 4096]
    const float* W = (const float*)d_in[1];   // [4096, 4096]
    const float* b = (const float*)d_in[2];   // [4096]
    float* out = (float*)d_out;

    void* fn = nullptr;
    cudaDriverEntryPointQueryResult qr;
    cudaGetDriverEntryPointByVersion("cuTensorMapEncodeTiled", &fn, 12000,
                                     cudaEnableDefault, &qr);
    PFN_encodeTiled enc = (PFN_encodeTiled)fn;

    void *pXhi, *pXlo, *pW8;
    cudaGetSymbolAddress(&pXhi, g_Xhi);
    cudaGetSymbolAddress(&pXlo, g_Xlo);
    cudaGetSymbolAddress(&pW8,  g_W8);

    CUtensorMap tmAhi, tmAlo, tmB;
    make_map2d(enc, &tmAhi, pXhi, Kdim, Mdim, KC, MT);
    make_map2d(enc, &tmAlo, pXlo, Kdim, Mdim, KC, MT);
    make_map2d(enc, &tmB,   pW8,  Kdim, Ndim, KC, 256);

    cudaFuncSetAttribute((const void*)gemm_kernel,
                         cudaFuncAttributeMaxDynamicSharedMemorySize, SMEM_TOTAL);

    int nW4 = (Ndim * Kdim) / 4;
    int nX4 = (Mdim * Kdim) / 4;

    k_init<<<1, 32>>>();
    k_absmax<<<512, 256>>>((const float4*)W, nW4);
    k_quant<<<2048, 256>>>((const float4*)W, nW4);
    k_split<<<4096, 256>>>((const float4*)x, nX4);
    gemm_kernel<<<(Mdim / MT) * (Ndim / NT), 128, SMEM_TOTAL>>>(
        tmAhi, tmAlo, tmB, b, out);
    // no-op (per-block early exit) when the tcgen05 image is loaded
    fallback_gemm<<<dim3(Ndim / 64, Mdim / 64), 256>>>(x, b, out);
}

// round 12
// speedup vs baseline: 1.0624x; 1.0624x over previous
#include <cuda_runtime.h>
#include <cuda.h>
#include <cuda_bf16.h>
#include <cstdint>

// ============================================================================
// y[8192,4096] = x @ Wq^T + b,  Wq = per-tensor int8 dequant of W.
// w_int exact in bf16 (8-bit int); x split hi+lo bf16; two accumulated bf16
// tcgen05 GEMMs into one fp32 TMEM accumulator; y = scale*acc + b.
//
// R12: cta_group::2 MMA over 2-CTA clusters. Pair tile = 256x512: per-pair L2
// delivery 8MB vs cg1's 12MB-equivalent -> chunks flip from mem-paced
// (2250cyc) to compute-paced (2048cyc). Follower->leader data-ready signal via
// relay warp (wait own TMA full, mapa-arrive leader's full, count=2) so the
// TMA path uses only plain ::cta loads. Leader issues cg2 MMAs; cg2 multicast
// commit releases both CTAs' stage buffers and the final done barrier.
//
// NOTE (R10 lesson): kind::i8 tcgen05 is NOT supported on sm_103a; W must be
// bf16 to carry 8 exact bits, so the bf16 hi/lo scheme is forced.
//
// tcgen05 PTX is arch-'a'-gated (harness has a compute_103 non-'a' pass);
// runtime probe + always-compiled fallback keep correctness either way.
// ============================================================================

#if defined(__CUDA_ARCH_FEAT_SM103_ALL) || defined(__CUDA_ARCH_FEAT_SM100_ALL) || \
    defined(__CUDA_ARCH_FEAT_SM101_ALL)
#define HAS_TCGEN05 1
#else
#define HAS_TCGEN05 0
#endif

static constexpr int Mdim = 8192, Ndim = 4096, Kdim = 4096;
static constexpr int MT2 = 256;                           // pair M tile
static constexpr int NT = 512, KC = 64;                   // pair N tile, K chunk
static constexpr int NCHUNK = Kdim / KC;                  // 64
static constexpr int STAGES = 3;
static constexpr int A_BYTES = 128 * 128;                 // 16384 per CTA (128 rows x 128B)
static constexpr int BQ_BYTES = 128 * 128;                // 16384 per B quarter
static constexpr int STAGE_BYTES = 2 * A_BYTES + 2 * BQ_BYTES; // 65536 per CTA
static constexpr int OFF_XHI = 0;
static constexpr int OFF_XLO = A_BYTES;                   // +16384
static constexpr int OFF_B   = 2 * A_BYTES;               // +32768 (two 16KB quarters)
static constexpr int SMEM_TOTAL = 1024 + STAGES * STAGE_BYTES; // 197632

// idesc kind::f16 cg2: dtype=F32, a=BF16, b=BF16, N=256, M=256
static constexpr uint32_t IDESC_CG2 =
    (1u << 4) | (1u << 7) | (1u << 10) | ((256u / 8) << 17) | ((256u / 16) << 24);

// ---------------- persistent scratch (no cudaMalloc allowed) ----------------
__device__ __align__(16) __nv_bfloat16 g_W8 [(size_t)Ndim * Kdim]; // 32MB
__device__ __align__(16) __nv_bfloat16 g_Xhi[(size_t)Mdim * Kdim]; // 64MB
__device__ __align__(16) __nv_bfloat16 g_Xlo[(size_t)Mdim * Kdim]; // 64MB
__device__ float    g_scale;
__device__ unsigned g_absmax;
__device__ int      g_use_tc;

// ---------------- PTX helpers ----------------
__device__ __forceinline__ uint32_t smem_to_u32(const void* p) {
    uint32_t a;
    asm("{ .reg .u64 t; cvta.to.shared.u64 t, %1; cvt.u32.u64 %0, t; }"
        : "=r"(a) : "l"(p));
    return a;
}

__device__ __forceinline__ uint32_t elect_one_pred() {
    uint32_t pred;
    asm volatile(
        "{\n\t.reg .pred p;\n\telect.sync _|p, 0xFFFFFFFF;\n\tselp.b32 %0, 1, 0, p;\n\t}"
        : "=r"(pred));
    return pred;
}

__device__ __forceinline__ uint32_t cluster_rank() {
    uint32_t r;
    asm("mov.u32 %0, %%cluster_ctarank;" : "=r"(r));
    return r;
}

#define CLUSTER_SYNC() do { \
    asm volatile("barrier.cluster.arrive.aligned;" ::: "memory"); \
    asm volatile("barrier.cluster.wait.aligned;"   ::: "memory"); \
} while (0)

#define MBARRIER_INIT(addr, cnt) \
    asm volatile("mbarrier.init.shared.b64 [%0], %1;" :: "r"((uint32_t)(addr)), "r"((uint32_t)(cnt)) : "memory")

#define MBARRIER_EXPECT_TX(addr, bytes) \
    asm volatile("mbarrier.arrive.expect_tx.shared.b64 _, [%0], %1;" :: "r"((uint32_t)(addr)), "r"((uint32_t)(bytes)) : "memory")

// arrive on the same-offset mbarrier in cluster CTA `rank`
#define MBARRIER_ARRIVE_CLUSTER(local_addr, rank) \
    asm volatile("{\n\t.reg .b32 ra;\n\tmapa.shared::cluster.u32 ra, %0, %1;\n\t" \
                 "mbarrier.arrive.shared::cluster.b64 _, [ra];\n\t}" \
        :: "r"((uint32_t)(local_addr)), "r"((uint32_t)(rank)) : "memory")

#define MBARRIER_WAIT_PARITY(addr, par) do { \
    uint32_t _m = (uint32_t)(addr), _p = (uint32_t)(par), _d; \
    asm volatile("{\n\t.reg .pred p;\n\tmbarrier.try_wait.parity.acquire.cta.shared::cta.b64 p, [%1], %2;\n\tselp.b32 %0, 1, 0, p;\n\t}" \
        : "=r"(_d) : "r"(_m), "r"(_p) : "memory"); \
    if (!_d) { \
        asm volatile("{\n\t.reg .pred P1;\n\tWL_%=:\n\tmbarrier.try_wait.parity.acquire.cta.shared::cta.b64 P1, [%0], %1, 0x989680;\n\t@P1 bra.uni WD_%=;\n\tbra.uni WL_%=;\n\tWD_%=:\n\t}" \
            :: "r"(_m), "r"(_p) : "memory"); \
    } \
} while (0)

#define MBARRIER_WAIT_PARITY_RELAXED(addr, par) do { \
    uint32_t _m = (uint32_t)(addr), _p = (uint32_t)(par), _d; \
    asm volatile("{\n\t.reg .pred p;\n\tmbarrier.try_wait.parity.relaxed.cta.shared::cta.b64 p, [%1], %2, 0x989680;\n\tselp.b32 %0, 1, 0, p;\n\t}" \
        : "=r"(_d) : "r"(_m), "r"(_p) : "memory"); \
    if (!_d) { \
        asm volatile("{\n\t.reg .pred P1;\n\tWL_%=:\n\tmbarrier.try_wait.parity.relaxed.cta.shared::cta.b64 P1, [%0], %1, 0x989680;\n\t@P1 bra.uni WD_%=;\n\tbra.uni WL_%=;\n\tWD_%=:\n\t}" \
            :: "r"(_m), "r"(_p) : "memory"); \
    } \
} while (0)

#define TCGEN05_ALLOC_CG2(smem_addr, n) \
    asm volatile("tcgen05.alloc.cta_group::2.sync.aligned.shared::cta.b32 [%0], %1;" \
        :: "r"((uint32_t)(smem_addr)), "r"((uint32_t)(n)) : "memory")

#define TCGEN05_DEALLOC_CG2(tmem, n) \
    asm volatile("tcgen05.dealloc.cta_group::2.sync.aligned.b32 %0, %1;" :: "r"(tmem), "r"((uint32_t)(n)))

#define TCGEN05_RELINQUISH_CG2() \
    asm volatile("tcgen05.relinquish_alloc_permit.cta_group::2.sync.aligned;")

// cg2 commit, multicast: arrives on same-offset mbarrier in every CTA in mask
#define TCGEN05_COMMIT_MC_CG2(mbar, mask) \
    asm volatile("tcgen05.commit.cta_group::2.mbarrier::arrive::one.shared::cluster.multicast::cluster.b64 [%0], %1;" \
        :: "r"((uint32_t)(mbar)), "h"((uint16_t)(mask)) : "memory")

#define TCGEN05_FENCE_AFTER() asm volatile("tcgen05.fence::after_thread_sync;" ::: "memory")
#define TCGEN05_WAIT_LD()     asm volatile("tcgen05.wait::ld.sync.aligned;" ::: "memory")

#define TCGEN05_LD_32X32B_X32(r, addr) \
    asm volatile("tcgen05.ld.sync.aligned.32x32b.x32.b32 " \
        "{%0, %1, %2, %3, %4, %5, %6, %7, %8, %9, %10, %11, %12, %13, %14, %15, " \
        " %16, %17, %18, %19, %20, %21, %22, %23, %24, %25, %26, %27, %28, %29, %30, %31}, [%32];" \
        : "=r"((r)[0]),  "=r"((r)[1]),  "=r"((r)[2]),  "=r"((r)[3]), \
          "=r"((r)[4]),  "=r"((r)[5]),  "=r"((r)[6]),  "=r"((r)[7]), \
          "=r"((r)[8]),  "=r"((r)[9]),  "=r"((r)[10]), "=r"((r)[11]), \
          "=r"((r)[12]), "=r"((r)[13]), "=r"((r)[14]), "=r"((r)[15]), \
          "=r"((r)[16]), "=r"((r)[17]), "=r"((r)[18]), "=r"((r)[19]), \
          "=r"((r)[20]), "=r"((r)[21]), "=r"((r)[22]), "=r"((r)[23]), \
          "=r"((r)[24]), "=r"((r)[25]), "=r"((r)[26]), "=r"((r)[27]), \
          "=r"((r)[28]), "=r"((r)[29]), "=r"((r)[30]), "=r"((r)[31]) \
        : "r"(addr))

#define TMA_LOAD_2D(smem, map, cx, cy, mbar) \
    asm volatile("cp.async.bulk.tensor.2d.shared::cta.global.tile.mbarrier::complete_tx::bytes " \
        "[%0], [%1, {%2, %3}], [%4];" \
        :: "r"((uint32_t)(smem)), "l"(map), "r"((int32_t)(cx)), "r"((int32_t)(cy)), \
           "r"((uint32_t)(mbar)) : "memory")

// SW128 K-major SMEM descriptor (Blackwell): layout=SW128, version=1, SBO=64, LBO=1
static constexpr uint64_t SMEM_DESC_BASE_SW128 =
    (uint64_t(2) << 61) | (uint64_t(1) << 46) | (uint64_t(64) << 32) | (uint64_t(1) << 16);
#define MAKE_SMEM_DESC(a) (SMEM_DESC_BASE_SW128 | ((uint64_t)((a) >> 4) & 0x3FFF))

#if HAS_TCGEN05
// SS bf16 MMA, cta_group::2 (M=256 across pair), fp32 accum.
// 8-reg zero disable-output-lane vector per the cg2 encoding.
__device__ __forceinline__ void mma_ss_f16_cg2(uint32_t d, uint64_t ad, uint64_t bd,
                                               uint32_t idesc, bool acc) {
    uint32_t en = acc ? 1u : 0u;
    asm volatile(
        "{\n\t.reg .pred p;\n\tsetp.ne.u32 p, %5, 0;\n\t"
        "tcgen05.mma.cta_group::2.kind::f16 [%0], %1, %2, %3, "
        "{%4, %4, %4, %4, %4, %4, %4, %4}, p;\n\t}"
        :: "r"(d), "l"(ad), "l"(bd), "r"(idesc), "r"(0u), "r"(en) : "memory");
}
#endif

// ---------------- prep kernels (arch-neutral) ----------------
__global__ void k_init() { g_absmax = 0u; g_use_tc = HAS_TCGEN05; }

__global__ void k_absmax(const float4* __restrict__ W4, int n4) {
    unsigned m = 0u;
    int stride = gridDim.x * blockDim.x;
    for (int i = blockIdx.x * blockDim.x + threadIdx.x; i < n4; i += stride) {
        float4 v = W4[i];
        m = max(m, __float_as_uint(fabsf(v.x)));
        m = max(m, __float_as_uint(fabsf(v.y)));
        m = max(m, __float_as_uint(fabsf(v.z)));
        m = max(m, __float_as_uint(fabsf(v.w)));
    }
    #pragma unroll
    for (int o = 16; o; o >>= 1) m = max(m, __shfl_xor_sync(0xffffffffu, m, o));
    __shared__ unsigned sm[8];
    if ((threadIdx.x & 31) == 0) sm[threadIdx.x >> 5] = m;
    __syncthreads();
    if (threadIdx.x == 0) {
        unsigned v = sm[0];
        #pragma unroll
        for (int w = 1; w < 8; w++) v = max(v, sm[w]);
        atomicMax(&g_absmax, v);
    }
}

union Pack4 { __nv_bfloat16 h[4]; uint2 u; };

__global__ void k_quant(const float4* __restrict__ W4, int n4) {
    float scale = __fdiv_rn(__uint_as_float(g_absmax), 127.0f);
    if (blockIdx.x == 0 && threadIdx.x == 0) g_scale = scale;
    int stride = gridDim.x * blockDim.x;
    for (int i = blockIdx.x * blockDim.x + threadIdx.x; i < n4; i += stride) {
        float4 v = W4[i];
        Pack4 p;
        p.h[0] = __float2bfloat16_rn(fminf(127.f, fmaxf(-127.f, rintf(__fdiv_rn(v.x, scale)))));
        p.h[1] = __float2bfloat16_rn(fminf(127.f, fmaxf(-127.f, rintf(__fdiv_rn(v.y, scale)))));
        p.h[2] = __float2bfloat16_rn(fminf(127.f, fmaxf(-127.f, rintf(__fdiv_rn(v.z, scale)))));
        p.h[3] = __float2bfloat16_rn(fminf(127.f, fmaxf(-127.f, rintf(__fdiv_rn(v.w, scale)))));
        reinterpret_cast<uint2*>(g_W8)[i] = p.u;
    }
}

__global__ void k_split(const float4* __restrict__ X4, int n4) {
    int stride = gridDim.x * blockDim.x;
    for (int i = blockIdx.x * blockDim.x + threadIdx.x; i < n4; i += stride) {
        float4 v = X4[i];
        Pack4 ph, pl;
        ph.h[0] = __float2bfloat16_rn(v.x); pl.h[0] = __float2bfloat16_rn(v.x - __bfloat162float(ph.h[0]));
        ph.h[1] = __float2bfloat16_rn(v.y); pl.h[1] = __float2bfloat16_rn(v.y - __bfloat162float(ph.h[1]));
        ph.h[2] = __float2bfloat16_rn(v.z); pl.h[2] = __float2bfloat16_rn(v.z - __bfloat162float(ph.h[2]));
        ph.h[3] = __float2bfloat16_rn(v.w); pl.h[3] = __float2bfloat16_rn(v.w - __bfloat162float(ph.h[3]));
        reinterpret_cast<uint2*>(g_Xhi)[i] = ph.u;
        reinterpret_cast<uint2*>(g_Xlo)[i] = pl.u;
    }
}

// ---------------- cg2 tcgen05 GEMM kernel ----------------------------------
// 2-CTA cluster = one 256x512 output tile. Per CTA, per K-chunk (64 elems):
//   A hi/lo: its 128 M-rows (16KB each); B: its two 128-row quarters
//   (dispatch nh needs W rows nt*512 + nh*256 + rank*128).
// warp0 (leader) = cg2 MMA issuer; warp1 = TMA producer (both CTAs);
// warp2 (follower) = full-barrier relay to leader; all warps = epilogue.
__global__ void __launch_bounds__(128, 1) __cluster_dims__(2, 1, 1)
gemm_kernel(
    const __grid_constant__ CUtensorMap tmXhi,
    const __grid_constant__ CUtensorMap tmXlo,
    const __grid_constant__ CUtensorMap tmB,
    const float* __restrict__ bias,
    float* __restrict__ out)
{
#if HAS_TCGEN05
    extern __shared__ char smem[];
    uint32_t sb  = smem_to_u32(smem);
    int tid = threadIdx.x, wid = tid >> 5, lid = tid & 31;

    uint32_t rank = cluster_rank();          // 0 = leader, 1 = follower
    int pair = blockIdx.x >> 1;
    int mt = pair >> 3, nt = pair & 7;       // n-fastest: 8 pairs share A rows

    const uint32_t TMEMP = sb;
    const uint32_t FULLB = sb + 8;           // full[0..2] @ +8,+16,+24
    const uint32_t EMPTB = sb + 32;          // empty[0..2] @ +32,+40,+48
    const uint32_t DONEB = sb + 56;

    if (wid == 0) TCGEN05_ALLOC_CG2(TMEMP, 512);
    if (tid == 0) {
        #pragma unroll
        for (int s = 0; s < STAGES; s++) {
            // leader full: expect_tx arrive (1) + follower relay arrive (1)
            MBARRIER_INIT(FULLB + s * 8, rank == 0 ? 2 : 1);
            MBARRIER_INIT(EMPTB + s * 8, 1);
        }
        MBARRIER_INIT(DONEB, 1);
    }
    __syncthreads();
    uint32_t tmem;
    asm volatile("ld.shared.b32 %0, [%1];" : "=r"(tmem) : "r"(TMEMP));
    if (wid == 0) TCGEN05_RELINQUISH_CG2();

    // barriers must be visible cluster-wide before relay arrivals / mc commits
    CLUSTER_SYNC();

    if (wid == 1) {
        // producer (both CTAs): load own A halves + own two B quarters
        if (elect_one_pred()) {
            int a_row = mt * MT2 + (int)rank * 128;
            int b_row0 = nt * NT + (int)rank * 128;        // quarter nh=0
            int b_row1 = nt * NT + 256 + (int)rank * 128;  // quarter nh=1
            for (int i = 0; i < NCHUNK; i++) {
                int s = i % STAGES, r = i / STAGES;
                uint32_t full = FULLB + s * 8;
                if (i >= STAGES)
                    MBARRIER_WAIT_PARITY_RELAXED(EMPTB + s * 8, (r - 1) & 1);
                MBARRIER_EXPECT_TX(full, STAGE_BYTES);     // own 64KB
                int k0 = i * KC;
                uint32_t base = sb + 1024 + s * STAGE_BYTES;
                TMA_LOAD_2D(base + OFF_XHI,          &tmXhi, k0, a_row,  full);
                TMA_LOAD_2D(base + OFF_XLO,          &tmXlo, k0, a_row,  full);
                TMA_LOAD_2D(base + OFF_B,            &tmB,   k0, b_row0, full);
                TMA_LOAD_2D(base + OFF_B + BQ_BYTES, &tmB,   k0, b_row1, full);
            }
        }
    } else if (wid == 2 && rank == 1) {
        // follower relay: own TMA done -> arrive on leader's full barrier
        if (elect_one_pred()) {
            for (int i = 0; i < NCHUNK; i++) {
                int s = i % STAGES, r = i / STAGES;
                MBARRIER_WAIT_PARITY_RELAXED(FULLB + s * 8, r & 1);
                MBARRIER_ARRIVE_CLUSTER(FULLB + s * 8, 0);
            }
        }
    } else if (wid == 0 && rank == 0) {
        // leader MMA issuer
        if (elect_one_pred()) {
            uint64_t dXhi[STAGES], dXlo[STAGES], dB[STAGES];
            #pragma unroll
            for (int s = 0; s < STAGES; s++) {
                uint32_t base = sb + 1024 + s * STAGE_BYTES;
                dXhi[s] = MAKE_SMEM_DESC(base + OFF_XHI);
                dXlo[s] = MAKE_SMEM_DESC(base + OFF_XLO);
                dB[s]   = MAKE_SMEM_DESC(base + OFF_B);
            }
            for (int i = 0; i < NCHUNK; i++) {
                int s = i % STAGES, r = i / STAGES;
                MBARRIER_WAIT_PARITY(FULLB + s * 8, r & 1);
                #pragma unroll
                for (int nh = 0; nh < 2; nh++) {
                    uint32_t d  = tmem + nh * 256;              // D cols [0,256),[256,512)
                    uint64_t bd = dB[s] + (uint64_t)nh * 1024;  // +16KB in 16B units
                    #pragma unroll
                    for (int ks = 0; ks < 4; ks++)              // hi half of x
                        mma_ss_f16_cg2(d, dXhi[s] + ks * 2, bd + ks * 2, IDESC_CG2,
                                       !(i == 0 && ks == 0));
                    #pragma unroll
                    for (int ks = 0; ks < 4; ks++)              // lo half of x
                        mma_ss_f16_cg2(d, dXlo[s] + ks * 2, bd + ks * 2, IDESC_CG2, true);
                }
                TCGEN05_COMMIT_MC_CG2(EMPTB + s * 8, 0x3);      // release both CTAs' stage s
            }
            TCGEN05_COMMIT_MC_CG2(DONEB, 0x3);                  // final: both CTAs
        }
    }

    __syncthreads();
    MBARRIER_WAIT_PARITY(DONEB, 0);
    TCGEN05_FENCE_AFTER();

    // epilogue: CTA rank holds D rows rank*128..+127; cols map 1:1 to features
    float scale = g_scale;
    size_t m = (size_t)(mt * MT2 + (int)rank * 128 + wid * 32 + lid);
    float* orow = out + m * Ndim + (size_t)nt * NT;
    const float* brow = bias + nt * NT;
    for (int cb = 0; cb < NT; cb += 32) {
        uint32_t r[32];
        TCGEN05_LD_32X32B_X32(r, tmem + cb);
        TCGEN05_WAIT_LD();
        float y[32];
        #pragma unroll
        for (int j = 0; j < 32; j++)
            y[j] = fmaf(scale, __uint_as_float(r[j]), __ldg(brow + cb + j));
        #pragma unroll
        for (int j = 0; j < 32; j += 4)
            *reinterpret_cast<float4*>(orow + cb + j) =
                make_float4(y[j], y[j + 1], y[j + 2], y[j + 3]);
    }

    __syncthreads();
    if (wid == 0) TCGEN05_DEALLOC_CG2(tmem, 512);
    // no CTA may exit while pair traffic could still target its SMEM/TMEM
    CLUSTER_SYNC();
#else
    (void)tmXhi; (void)tmXlo; (void)tmB; (void)bias; (void)out;
#endif
}

// ---------------- always-compiled fallback GEMM (runs only if stub image) ---
__global__ void __launch_bounds__(256) fallback_gemm(
    const float* __restrict__ x, const float* __restrict__ bias,
    float* __restrict__ out)
{
    if (g_use_tc) return;   // tcgen05 path already produced the result

    __shared__ float As[16][68];
    __shared__ float Bs[16][68];

    int tid = threadIdx.x;
    int tx = tid & 15, ty = tid >> 4;
    int n0 = blockIdx.x * 64, m0 = blockIdx.y * 64;
    float scale = g_scale;

    float acc[4][4];
    #pragma unroll
    for (int i = 0; i < 4; i++)
        #pragma unroll
        for (int j = 0; j < 4; j++) acc[i][j] = 0.f;

    int lrow = tid >> 2;
    int lk4  = (tid & 3) * 4;

    for (int k0 = 0; k0 < Kdim; k0 += 16) {
        float4 av = *reinterpret_cast<const float4*>(
            x + (size_t)(m0 + lrow) * Kdim + k0 + lk4);
        As[lk4 + 0][lrow] = av.x; As[lk4 + 1][lrow] = av.y;
        As[lk4 + 2][lrow] = av.z; As[lk4 + 3][lrow] = av.w;
        uint2 bu = *reinterpret_cast<const uint2*>(
            g_W8 + (size_t)(n0 + lrow) * Kdim + k0 + lk4);
        Pack4 bp; bp.u = bu;
        Bs[lk4 + 0][lrow] = __bfloat162float(bp.h[0]);
        Bs[lk4 + 1][lrow] = __bfloat162float(bp.h[1]);
        Bs[lk4 + 2][lrow] = __bfloat162float(bp.h[2]);
        Bs[lk4 + 3][lrow] = __bfloat162float(bp.h[3]);
        __syncthreads();

        #pragma unroll
        for (int k = 0; k < 16; k++) {
            float a[4], bb[4];
            #pragma unroll
            for (int i = 0; i < 4; i++) a[i]  = As[k][ty * 4 + i];
            #pragma unroll
            for (int j = 0; j < 4; j++) bb[j] = Bs[k][tx * 4 + j];
            #pragma unroll
            for (int i = 0; i < 4; i++)
                #pragma unroll
                for (int j = 0; j < 4; j++)
                    acc[i][j] = fmaf(a[i], bb[j], acc[i][j]);
        }
        __syncthreads();
    }

    #pragma unroll
    for (int i = 0; i < 4; i++) {
        size_t m = (size_t)(m0 + ty * 4 + i);
        #pragma unroll
        for (int j = 0; j < 4; j++) {
            int n = n0 + tx * 4 + j;
            out[m * Ndim + n] = fmaf(scale, acc[i][j], __ldg(bias + n));
        }
    }
}

// ---------------- host launch ----------------
typedef CUresult (*PFN_encodeTiled)(
    CUtensorMap*, CUtensorMapDataType, cuuint32_t, void*,
    const cuuint64_t*, const cuuint64_t*, const cuuint32_t*, const cuuint32_t*,
    CUtensorMapInterleave, CUtensorMapSwizzle, CUtensorMapL2promotion,
    CUtensorMapFloatOOBfill);

static void make_map2d(PFN_encodeTiled enc, CUtensorMap* tm, void* ptr,
                       uint64_t d0, uint64_t d1, uint32_t b0, uint32_t b1) {
    cuuint64_t dims[2]    = {d0, d1};
    cuuint64_t strides[1] = {d0 * 2};  // bf16, K-major contiguous
    cuuint32_t box[2]     = {b0, b1};
    cuuint32_t es[2]      = {1, 1};
    enc(tm, CU_TENSOR_MAP_DATA_TYPE_BFLOAT16, 2, ptr, dims, strides, box, es,
        CU_TENSOR_MAP_INTERLEAVE_NONE, CU_TENSOR_MAP_SWIZZLE_128B,
        CU_TENSOR_MAP_L2_PROMOTION_L2_128B, CU_TENSOR_MAP_FLOAT_OOB_FILL_NONE);
}

extern "C" void kernel_launch(void* const* d_in, const int* in_sizes, int n_in,
                              void* d_out, int out_size) {
    const float* x = (const float*)d_in[0];   // [8192, 4096]
    const float* W = (const float*)d_in[1];   // [4096, 4096]
    const float* b = (const float*)d_in[2];   // [4096]
    float* out = (float*)d_out;

    void* fn = nullptr;
    cudaDriverEntryPointQueryResult qr;
    cudaGetDriverEntryPointByVersion("cuTensorMapEncodeTiled", &fn, 12000,
                                     cudaEnableDefault, &qr);
    PFN_encodeTiled enc = (PFN_encodeTiled)fn;

    void *pXhi, *pXlo, *pW8;
    cudaGetSymbolAddress(&pXhi, g_Xhi);
    cudaGetSymbolAddress(&pXlo, g_Xlo);
    cudaGetSymbolAddress(&pW8,  g_W8);

    CUtensorMap tmXhi, tmXlo, tmB;
    make_map2d(enc, &tmXhi, pXhi, Kdim, Mdim, KC, 128);
    make_map2d(enc, &tmXlo, pXlo, Kdim, Mdim, KC, 128);
    make_map2d(enc, &tmB,   pW8,  Kdim, Ndim, KC, 128);

    cudaFuncSetAttribute((const void*)gemm_kernel,
                         cudaFuncAttributeMaxDynamicSharedMemorySize, SMEM_TOTAL);

    int nW4 = (Ndim * Kdim) / 4;
    int nX4 = (Mdim * Kdim) / 4;

    k_init<<<1, 32>>>();
    k_absmax<<<512, 256>>>((const float4*)W, nW4);
    k_quant<<<2048, 256>>>((const float4*)W, nW4);
    k_split<<<4096, 256>>>((const float4*)x, nX4);
    gemm_kernel<<<(Mdim / MT2) * (Ndim / NT) * 2, 128, SMEM_TOTAL>>>(
        tmXhi, tmXlo, tmB, b, out);
    // no-op (per-block early exit) when the tcgen05 image is loaded
    fallback_gemm<<<dim3(Ndim / 64, Mdim / 64), 256>>>(x, b, out);
}

// round 16
// speedup vs baseline: 1.0779x; 1.0146x over previous
#include <cuda_runtime.h>
#include <cuda.h>
#include <cuda_bf16.h>
#include <cstdint>

// ============================================================================
// y[8192,4096] = x @ Wq^T + b,  Wq = per-tensor int8 dequant of W.
// w_int exact in bf16; x split hi+lo bf16; two accumulated cg2 bf16 tcgen05
// GEMMs into one fp32 TMEM accumulator; y = scale*acc + b.
//
// R14 = R13 (persistent pairs) + epilogue TMEM-subpartition fix:
// tcgen05.ld accesses lanes of subpartition (warp_id % 4); epilogue warps
// 2..5 must write rows (wid&3)*32, not (wid-2)*32. R13 scrambled rows.
//
// Persistent pairs: 74 fixed 2-CTA clusters each process 3-4 256x512 tiles.
// TMEM alloc, barrier init, cluster syncs, pipeline fill once per pair;
// producer/relay stream chunks across tile boundaries; next tile's MMA waits
// epilogue-done (TMEM D reuse). Roles: w0 = MMA(leader)/relay(follower),
// w1 = TMA producer, w2-5 = epilogue. (R10 lesson: kind::i8 unsupported.)
// ============================================================================

#if defined(__CUDA_ARCH_FEAT_SM103_ALL) || defined(__CUDA_ARCH_FEAT_SM100_ALL) || \
    defined(__CUDA_ARCH_FEAT_SM101_ALL)
#define HAS_TCGEN05 1
#else
#define HAS_TCGEN05 0
#endif

static constexpr int Mdim = 8192, Ndim = 4096, Kdim = 4096;
static constexpr int MT2 = 256;                           // pair M tile
static constexpr int NT = 512, KC = 64;                   // pair N tile, K chunk
static constexpr int NCHUNK = Kdim / KC;                  // 64
static constexpr int STAGES = 3;
static constexpr int NPAIRS = 74;
static constexpr int NTILES = (Mdim / MT2) * (Ndim / NT); // 256
static constexpr int A_BYTES = 128 * 128;                 // 16384 per CTA
static constexpr int BQ_BYTES = 128 * 128;                // 16384 per B quarter
static constexpr int STAGE_BYTES = 2 * A_BYTES + 2 * BQ_BYTES; // 65536 per CTA
static constexpr int OFF_XHI = 0;
static constexpr int OFF_XLO = A_BYTES;
static constexpr int OFF_B   = 2 * A_BYTES;
static constexpr int SMEM_TOTAL = 1024 + STAGES * STAGE_BYTES; // 197632

// idesc kind::f16 cg2: dtype=F32, a=BF16, b=BF16, N=256, M=256
static constexpr uint32_t IDESC_CG2 =
    (1u << 4) | (1u << 7) | (1u << 10) | ((256u / 8) << 17) | ((256u / 16) << 24);

// ---------------- persistent scratch (no cudaMalloc allowed) ----------------
__device__ __align__(16) __nv_bfloat16 g_W8 [(size_t)Ndim * Kdim]; // 32MB
__device__ __align__(16) __nv_bfloat16 g_Xhi[(size_t)Mdim * Kdim]; // 64MB
__device__ __align__(16) __nv_bfloat16 g_Xlo[(size_t)Mdim * Kdim]; // 64MB
__device__ float    g_scale;
__device__ unsigned g_absmax;
__device__ int      g_use_tc;

// ---------------- PTX helpers ----------------
__device__ __forceinline__ uint32_t smem_to_u32(const void* p) {
    uint32_t a;
    asm("{ .reg .u64 t; cvta.to.shared.u64 t, %1; cvt.u32.u64 %0, t; }"
        : "=r"(a) : "l"(p));
    return a;
}

__device__ __forceinline__ uint32_t elect_one_pred() {
    uint32_t pred;
    asm volatile(
        "{\n\t.reg .pred p;\n\telect.sync _|p, 0xFFFFFFFF;\n\tselp.b32 %0, 1, 0, p;\n\t}"
        : "=r"(pred));
    return pred;
}

__device__ __forceinline__ uint32_t cluster_rank() {
    uint32_t r;
    asm("mov.u32 %0, %%cluster_ctarank;" : "=r"(r));
    return r;
}

#define CLUSTER_SYNC() do { \
    asm volatile("barrier.cluster.arrive.aligned;" ::: "memory"); \
    asm volatile("barrier.cluster.wait.aligned;"   ::: "memory"); \
} while (0)

#define MBARRIER_INIT(addr, cnt) \
    asm volatile("mbarrier.init.shared.b64 [%0], %1;" :: "r"((uint32_t)(addr)), "r"((uint32_t)(cnt)) : "memory")

#define MBARRIER_EXPECT_TX(addr, bytes) \
    asm volatile("mbarrier.arrive.expect_tx.shared.b64 _, [%0], %1;" :: "r"((uint32_t)(addr)), "r"((uint32_t)(bytes)) : "memory")

// arrive on the same-offset mbarrier in cluster CTA `rank`
#define MBARRIER_ARRIVE_CLUSTER(local_addr, rank) \
    asm volatile("{\n\t.reg .b32 ra;\n\tmapa.shared::cluster.u32 ra, %0, %1;\n\t" \
                 "mbarrier.arrive.shared::cluster.b64 _, [ra];\n\t}" \
        :: "r"((uint32_t)(local_addr)), "r"((uint32_t)(rank)) : "memory")

#define MBARRIER_WAIT_PARITY(addr, par) do { \
    uint32_t _m = (uint32_t)(addr), _p = (uint32_t)(par), _d; \
    asm volatile("{\n\t.reg .pred p;\n\tmbarrier.try_wait.parity.acquire.cta.shared::cta.b64 p, [%1], %2;\n\tselp.b32 %0, 1, 0, p;\n\t}" \
        : "=r"(_d) : "r"(_m), "r"(_p) : "memory"); \
    if (!_d) { \
        asm volatile("{\n\t.reg .pred P1;\n\tWL_%=:\n\tmbarrier.try_wait.parity.acquire.cta.shared::cta.b64 P1, [%0], %1, 0x989680;\n\t@P1 bra.uni WD_%=;\n\tbra.uni WL_%=;\n\tWD_%=:\n\t}" \
            :: "r"(_m), "r"(_p) : "memory"); \
    } \
} while (0)

#define MBARRIER_WAIT_PARITY_RELAXED(addr, par) do { \
    uint32_t _m = (uint32_t)(addr), _p = (uint32_t)(par), _d; \
    asm volatile("{\n\t.reg .pred p;\n\tmbarrier.try_wait.parity.relaxed.cta.shared::cta.b64 p, [%1], %2, 0x989680;\n\tselp.b32 %0, 1, 0, p;\n\t}" \
        : "=r"(_d) : "r"(_m), "r"(_p) : "memory"); \
    if (!_d) { \
        asm volatile("{\n\t.reg .pred P1;\n\tWL_%=:\n\tmbarrier.try_wait.parity.relaxed.cta.shared::cta.b64 P1, [%0], %1, 0x989680;\n\t@P1 bra.uni WD_%=;\n\tbra.uni WL_%=;\n\tWD_%=:\n\t}" \
            :: "r"(_m), "r"(_p) : "memory"); \
    } \
} while (0)

#define TCGEN05_ALLOC_CG2(smem_addr, n) \
    asm volatile("tcgen05.alloc.cta_group::2.sync.aligned.shared::cta.b32 [%0], %1;" \
        :: "r"((uint32_t)(smem_addr)), "r"((uint32_t)(n)) : "memory")

#define TCGEN05_DEALLOC_CG2(tmem, n) \
    asm volatile("tcgen05.dealloc.cta_group::2.sync.aligned.b32 %0, %1;" :: "r"(tmem), "r"((uint32_t)(n)))

#define TCGEN05_RELINQUISH_CG2() \
    asm volatile("tcgen05.relinquish_alloc_permit.cta_group::2.sync.aligned;")

#define TCGEN05_COMMIT_MC_CG2(mbar, mask) \
    asm volatile("tcgen05.commit.cta_group::2.mbarrier::arrive::one.shared::cluster.multicast::cluster.b64 [%0], %1;" \
        :: "r"((uint32_t)(mbar)), "h"((uint16_t)(mask)) : "memory")

#define TCGEN05_FENCE_AFTER()  asm volatile("tcgen05.fence::after_thread_sync;" ::: "memory")
#define TCGEN05_FENCE_BEFORE() asm volatile("tcgen05.fence::before_thread_sync;" ::: "memory")
#define TCGEN05_WAIT_LD()      asm volatile("tcgen05.wait::ld.sync.aligned;" ::: "memory")

#define TCGEN05_LD_32X32B_X32(r, addr) \
    asm volatile("tcgen05.ld.sync.aligned.32x32b.x32.b32 " \
        "{%0, %1, %2, %3, %4, %5, %6, %7, %8, %9, %10, %11, %12, %13, %14, %15, " \
        " %16, %17, %18, %19, %20, %21, %22, %23, %24, %25, %26, %27, %28, %29, %30, %31}, [%32];" \
        : "=r"((r)[0]),  "=r"((r)[1]),  "=r"((r)[2]),  "=r"((r)[3]), \
          "=r"((r)[4]),  "=r"((r)[5]),  "=r"((r)[6]),  "=r"((r)[7]), \
          "=r"((r)[8]),  "=r"((r)[9]),  "=r"((r)[10]), "=r"((r)[11]), \
          "=r"((r)[12]), "=r"((r)[13]), "=r"((r)[14]), "=r"((r)[15]), \
          "=r"((r)[16]), "=r"((r)[17]), "=r"((r)[18]), "=r"((r)[19]), \
          "=r"((r)[20]), "=r"((r)[21]), "=r"((r)[22]), "=r"((r)[23]), \
          "=r"((r)[24]), "=r"((r)[25]), "=r"((r)[26]), "=r"((r)[27]), \
          "=r"((r)[28]), "=r"((r)[29]), "=r"((r)[30]), "=r"((r)[31]) \
        : "r"(addr))

#define TMA_LOAD_2D(smem, map, cx, cy, mbar) \
    asm volatile("cp.async.bulk.tensor.2d.shared::cta.global.tile.mbarrier::complete_tx::bytes " \
        "[%0], [%1, {%2, %3}], [%4];" \
        :: "r"((uint32_t)(smem)), "l"(map), "r"((int32_t)(cx)), "r"((int32_t)(cy)), \
           "r"((uint32_t)(mbar)) : "memory")

static constexpr uint64_t SMEM_DESC_BASE_SW128 =
    (uint64_t(2) << 61) | (uint64_t(1) << 46) | (uint64_t(64) << 32) | (uint64_t(1) << 16);
#define MAKE_SMEM_DESC(a) (SMEM_DESC_BASE_SW128 | ((uint64_t)((a) >> 4) & 0x3FFF))

#if HAS_TCGEN05
__device__ __forceinline__ void mma_ss_f16_cg2(uint32_t d, uint64_t ad, uint64_t bd,
                                               uint32_t idesc, bool acc) {
    uint32_t en = acc ? 1u : 0u;
    asm volatile(
        "{\n\t.reg .pred p;\n\tsetp.ne.u32 p, %5, 0;\n\t"
        "tcgen05.mma.cta_group::2.kind::f16 [%0], %1, %2, %3, "
        "{%4, %4, %4, %4, %4, %4, %4, %4}, p;\n\t}"
        :: "r"(d), "l"(ad), "l"(bd), "r"(idesc), "r"(0u), "r"(en) : "memory");
}
#endif

// ---------------- prep kernels (arch-neutral) ----------------
__global__ void k_init() { g_absmax = 0u; g_use_tc = HAS_TCGEN05; }

__global__ void k_absmax(const float4* __restrict__ W4, int n4) {
    unsigned m = 0u;
    int stride = gridDim.x * blockDim.x;
    for (int i = blockIdx.x * blockDim.x + threadIdx.x; i < n4; i += stride) {
        float4 v = W4[i];
        m = max(m, __float_as_uint(fabsf(v.x)));
        m = max(m, __float_as_uint(fabsf(v.y)));
        m = max(m, __float_as_uint(fabsf(v.z)));
        m = max(m, __float_as_uint(fabsf(v.w)));
    }
    #pragma unroll
    for (int o = 16; o; o >>= 1) m = max(m, __shfl_xor_sync(0xffffffffu, m, o));
    __shared__ unsigned sm[8];
    if ((threadIdx.x & 31) == 0) sm[threadIdx.x >> 5] = m;
    __syncthreads();
    if (threadIdx.x == 0) {
        unsigned v = sm[0];
        #pragma unroll
        for (int w = 1; w < 8; w++) v = max(v, sm[w]);
        atomicMax(&g_absmax, v);
    }
}

union Pack4 { __nv_bfloat16 h[4]; uint2 u; };

__global__ void k_quant(const float4* __restrict__ W4, int n4) {
    float scale = __fdiv_rn(__uint_as_float(g_absmax), 127.0f);
    if (blockIdx.x == 0 && threadIdx.x == 0) g_scale = scale;
    int stride = gridDim.x * blockDim.x;
    for (int i = blockIdx.x * blockDim.x + threadIdx.x; i < n4; i += stride) {
        float4 v = W4[i];
        Pack4 p;
        p.h[0] = __float2bfloat16_rn(fminf(127.f, fmaxf(-127.f, rintf(__fdiv_rn(v.x, scale)))));
        p.h[1] = __float2bfloat16_rn(fminf(127.f, fmaxf(-127.f, rintf(__fdiv_rn(v.y, scale)))));
        p.h[2] = __float2bfloat16_rn(fminf(127.f, fmaxf(-127.f, rintf(__fdiv_rn(v.z, scale)))));
        p.h[3] = __float2bfloat16_rn(fminf(127.f, fmaxf(-127.f, rintf(__fdiv_rn(v.w, scale)))));
        reinterpret_cast<uint2*>(g_W8)[i] = p.u;
    }
}

__global__ void k_split(const float4* __restrict__ X4, int n4) {
    int stride = gridDim.x * blockDim.x;
    for (int i = blockIdx.x * blockDim.x + threadIdx.x; i < n4; i += stride) {
        float4 v = X4[i];
        Pack4 ph, pl;
        ph.h[0] = __float2bfloat16_rn(v.x); pl.h[0] = __float2bfloat16_rn(v.x - __bfloat162float(ph.h[0]));
        ph.h[1] = __float2bfloat16_rn(v.y); pl.h[1] = __float2bfloat16_rn(v.y - __bfloat162float(ph.h[1]));
        ph.h[2] = __float2bfloat16_rn(v.z); pl.h[2] = __float2bfloat16_rn(v.z - __bfloat162float(ph.h[2]));
        ph.h[3] = __float2bfloat16_rn(v.w); pl.h[3] = __float2bfloat16_rn(v.w - __bfloat162float(ph.h[3]));
        reinterpret_cast<uint2*>(g_Xhi)[i] = ph.u;
        reinterpret_cast<uint2*>(g_Xlo)[i] = pl.u;
    }
}

// ---------------- persistent cg2 tcgen05 GEMM ------------------------------
// 74 pairs; pair p handles tiles t = p, p+74, ... (3-4 tiles of 256x512).
// Per CTA roles: w0 = MMA issuer (leader) / full-relay (follower),
// w1 = TMA producer, w2..w5 = epilogue warps.
__global__ void __launch_bounds__(192, 1) __cluster_dims__(2, 1, 1)
gemm_kernel(
    const __grid_constant__ CUtensorMap tmXhi,
    const __grid_constant__ CUtensorMap tmXlo,
    const __grid_constant__ CUtensorMap tmB,
    const float* __restrict__ bias,
    float* __restrict__ out)
{
#if HAS_TCGEN05
    extern __shared__ char smem[];
    uint32_t sb  = smem_to_u32(smem);
    int tid = threadIdx.x, wid = tid >> 5, lid = tid & 31;

    uint32_t rank = cluster_rank();          // 0 = leader, 1 = follower
    int p = blockIdx.x >> 1;                 // pair id [0,74)
    int ntl = (NTILES - p + NPAIRS - 1) / NPAIRS;  // 4 if p<34 else 3

    const uint32_t TMEMP = sb;
    const uint32_t FULLB = sb + 8;           // full[0..2] @ +8,+16,+24
    const uint32_t EMPTB = sb + 32;          // empty[0..2] @ +32,+40,+48
    const uint32_t DONEB = sb + 56;
    const uint32_t EPIDB = sb + 64;          // epilogue-done (count=8, leader's used)

    if (wid == 0) TCGEN05_ALLOC_CG2(TMEMP, 512);
    if (tid == 0) {
        #pragma unroll
        for (int s = 0; s < STAGES; s++) {
            MBARRIER_INIT(FULLB + s * 8, rank == 0 ? 2 : 1);
            MBARRIER_INIT(EMPTB + s * 8, 1);
        }
        MBARRIER_INIT(DONEB, 1);
        MBARRIER_INIT(EPIDB, 8);             // 4 epilogue warps x 2 CTAs
    }
    __syncthreads();
    uint32_t tmem;
    asm volatile("ld.shared.b32 %0, [%1];" : "=r"(tmem) : "r"(TMEMP));
    if (wid == 0) TCGEN05_RELINQUISH_CG2();

    CLUSTER_SYNC();   // barriers visible cluster-wide before relay/mc commits

    if (wid == 1) {
        // ---- producer: stream all chunks of all tiles ----
        if (elect_one_pred()) {
            int c = 0;
            for (int lt = 0; lt < ntl; lt++) {
                int t = p + lt * NPAIRS;
                int mt = t >> 3, nt = t & 7;
                int a_row  = mt * MT2 + (int)rank * 128;
                int b_row0 = nt * NT + (int)rank * 128;
                int b_row1 = nt * NT + 256 + (int)rank * 128;
                for (int i = 0; i < NCHUNK; i++, c++) {
                    int s = c % STAGES, r = c / STAGES;
                    uint32_t full = FULLB + s * 8;
                    if (c >= STAGES)
                        MBARRIER_WAIT_PARITY_RELAXED(EMPTB + s * 8, (r - 1) & 1);
                    MBARRIER_EXPECT_TX(full, STAGE_BYTES);
                    int k0 = i * KC;
                    uint32_t base = sb + 1024 + s * STAGE_BYTES;
                    TMA_LOAD_2D(base + OFF_XHI,          &tmXhi, k0, a_row,  full);
                    TMA_LOAD_2D(base + OFF_XLO,          &tmXlo, k0, a_row,  full);
                    TMA_LOAD_2D(base + OFF_B,            &tmB,   k0, b_row0, full);
                    TMA_LOAD_2D(base + OFF_B + BQ_BYTES, &tmB,   k0, b_row1, full);
                }
            }
        }
    } else if (wid == 0 && rank == 1) {
        // ---- follower relay: own TMA done -> arrive on leader's full ----
        if (elect_one_pred()) {
            int ctot = ntl * NCHUNK;
            for (int c = 0; c < ctot; c++) {
                int s = c % STAGES, r = c / STAGES;
                MBARRIER_WAIT_PARITY_RELAXED(FULLB + s * 8, r & 1);
                MBARRIER_ARRIVE_CLUSTER(FULLB + s * 8, 0);
            }
        }
    } else if (wid == 0 && rank == 0) {
        // ---- leader MMA issuer ----
        if (elect_one_pred()) {
            uint64_t dXhi[STAGES], dXlo[STAGES], dB[STAGES];
            #pragma unroll
            for (int s = 0; s < STAGES; s++) {
                uint32_t base = sb + 1024 + s * STAGE_BYTES;
                dXhi[s] = MAKE_SMEM_DESC(base + OFF_XHI);
                dXlo[s] = MAKE_SMEM_DESC(base + OFF_XLO);
                dB[s]   = MAKE_SMEM_DESC(base + OFF_B);
            }
            int c = 0;
            for (int lt = 0; lt < ntl; lt++) {
                if (lt > 0) {   // TMEM D reuse: previous tile's epilogue must finish
                    MBARRIER_WAIT_PARITY(EPIDB, (lt - 1) & 1);
                    TCGEN05_FENCE_AFTER();
                }
                for (int i = 0; i < NCHUNK; i++, c++) {
                    int s = c % STAGES;
                    MBARRIER_WAIT_PARITY(FULLB + s * 8, (c / STAGES) & 1);
                    #pragma unroll
                    for (int nh = 0; nh < 2; nh++) {
                        uint32_t d  = tmem + nh * 256;
                        uint64_t bd = dB[s] + (uint64_t)nh * 1024;   // +16KB /16B
                        #pragma unroll
                        for (int ks = 0; ks < 4; ks++)
                            mma_ss_f16_cg2(d, dXhi[s] + ks * 2, bd + ks * 2, IDESC_CG2,
                                           !(i == 0 && ks == 0));
                        #pragma unroll
                        for (int ks = 0; ks < 4; ks++)
                            mma_ss_f16_cg2(d, dXlo[s] + ks * 2, bd + ks * 2, IDESC_CG2, true);
                    }
                    TCGEN05_COMMIT_MC_CG2(EMPTB + s * 8, 0x3);
                }
                TCGEN05_COMMIT_MC_CG2(DONEB, 0x3);   // per-tile done, parity = lt&1
            }
        }
    } else if (wid >= 2) {
        // ---- epilogue warps (both CTAs): per tile, read D + store ----
        // TMEM subpartition is warp_id % 4 (hardware-bound): warp w reads
        // lanes (w&3)*32..+31, so it must write exactly those output rows.
        float scale = g_scale;
        int row = (wid & 3) * 32 + lid;              // subpartition-correct row
        for (int lt = 0; lt < ntl; lt++) {
            int t = p + lt * NPAIRS;
            int mt = t >> 3, nt = t & 7;
            MBARRIER_WAIT_PARITY(DONEB, lt & 1);
            TCGEN05_FENCE_AFTER();

            size_t m = (size_t)(mt * MT2 + (int)rank * 128 + row);
            float* orow = out + m * Ndim + (size_t)nt * NT;
            const float* brow = bias + nt * NT;
            for (int cb = 0; cb < NT; cb += 32) {
                uint32_t r[32];
                TCGEN05_LD_32X32B_X32(r, tmem + cb);
                TCGEN05_WAIT_LD();
                float y[32];
                #pragma unroll
                for (int j = 0; j < 32; j++)
                    y[j] = fmaf(scale, __uint_as_float(r[j]), __ldg(brow + cb + j));
                #pragma unroll
                for (int j = 0; j < 32; j += 4)
                    *reinterpret_cast<float4*>(orow + cb + j) =
                        make_float4(y[j], y[j + 1], y[j + 2], y[j + 3]);
            }
            TCGEN05_FENCE_BEFORE();
            if (lid == 0) MBARRIER_ARRIVE_CLUSTER(EPIDB, 0);  // leader collects 8
        }
    }

    __syncthreads();
    if (wid == 0) TCGEN05_DEALLOC_CG2(tmem, 512);
    CLUSTER_SYNC();
#else
    (void)tmXhi; (void)tmXlo; (void)tmB; (void)bias; (void)out;
#endif
}

// ---------------- always-compiled fallback GEMM (runs only if stub image) ---
__global__ void __launch_bounds__(256) fallback_gemm(
    const float* __restrict__ x, const float* __restrict__ bias,
    float* __restrict__ out)
{
    if (g_use_tc) return;   // tcgen05 path already produced the result

    __shared__ float As[16][68];
    __shared__ float Bs[16][68];

    int tid = threadIdx.x;
    int tx = tid & 15, ty = tid >> 4;
    int n0 = blockIdx.x * 64, m0 = blockIdx.y * 64;
    float scale = g_scale;

    float acc[4][4];
    #pragma unroll
    for (int i = 0; i < 4; i++)
        #pragma unroll
        for (int j = 0; j < 4; j++) acc[i][j] = 0.f;

    int lrow = tid >> 2;
    int lk4  = (tid & 3) * 4;

    for (int k0 = 0; k0 < Kdim; k0 += 16) {
        float4 av = *reinterpret_cast<const float4*>(
            x + (size_t)(m0 + lrow) * Kdim + k0 + lk4);
        As[lk4 + 0][lrow] = av.x; As[lk4 + 1][lrow] = av.y;
        As[lk4 + 2][lrow] = av.z; As[lk4 + 3][lrow] = av.w;
        uint2 bu = *reinterpret_cast<const uint2*>(
            g_W8 + (size_t)(n0 + lrow) * Kdim + k0 + lk4);
        Pack4 bp; bp.u = bu;
        Bs[lk4 + 0][lrow] = __bfloat162float(bp.h[0]);
        Bs[lk4 + 1][lrow] = __bfloat162float(bp.h[1]);
        Bs[lk4 + 2][lrow] = __bfloat162float(bp.h[2]);
        Bs[lk4 + 3][lrow] = __bfloat162float(bp.h[3]);
        __syncthreads();

        #pragma unroll
        for (int k = 0; k < 16; k++) {
            float a[4], bb[4];
            #pragma unroll
            for (int i = 0; i < 4; i++) a[i]  = As[k][ty * 4 + i];
            #pragma unroll
            for (int j = 0; j < 4; j++) bb[j] = Bs[k][tx * 4 + j];
            #pragma unroll
            for (int i = 0; i < 4; i++)
                #pragma unroll
                for (int j = 0; j < 4; j++)
                    acc[i][j] = fmaf(a[i], bb[j], acc[i][j]);
        }
        __syncthreads();
    }

    #pragma unroll
    for (int i = 0; i < 4; i++) {
        size_t m = (size_t)(m0 + ty * 4 + i);
        #pragma unroll
        for (int j = 0; j < 4; j++) {
            int n = n0 + tx * 4 + j;
            out[m * Ndim + n] = fmaf(scale, acc[i][j], __ldg(bias + n));
        }
    }
}

// ---------------- host launch ----------------
typedef CUresult (*PFN_encodeTiled)(
    CUtensorMap*, CUtensorMapDataType, cuuint32_t, void*,
    const cuuint64_t*, const cuuint64_t*, const cuuint32_t*, const cuuint32_t*,
    CUtensorMapInterleave, CUtensorMapSwizzle, CUtensorMapL2promotion,
    CUtensorMapFloatOOBfill);

static void make_map2d(PFN_encodeTiled enc, CUtensorMap* tm, void* ptr,
                       uint64_t d0, uint64_t d1, uint32_t b0, uint32_t b1) {
    cuuint64_t dims[2]    = {d0, d1};
    cuuint64_t strides[1] = {d0 * 2};  // bf16, K-major contiguous
    cuuint32_t box[2]     = {b0, b1};
    cuuint32_t es[2]      = {1, 1};
    enc(tm, CU_TENSOR_MAP_DATA_TYPE_BFLOAT16, 2, ptr, dims, strides, box, es,
        CU_TENSOR_MAP_INTERLEAVE_NONE, CU_TENSOR_MAP_SWIZZLE_128B,
        CU_TENSOR_MAP_L2_PROMOTION_L2_128B, CU_TENSOR_MAP_FLOAT_OOB_FILL_NONE);
}

extern "C" void kernel_launch(void* const* d_in, const int* in_sizes, int n_in,
                              void* d_out, int out_size) {
    const float* x = (const float*)d_in[0];   // [8192, 4096]
    const float* W = (const float*)d_in[1];   // [4096, 4096]
    const float* b = (const float*)d_in[2];   // [4096]
    float* out = (float*)d_out;

    void* fn = nullptr;
    cudaDriverEntryPointQueryResult qr;
    cudaGetDriverEntryPointByVersion("cuTensorMapEncodeTiled", &fn, 12000,
                                     cudaEnableDefault, &qr);
    PFN_encodeTiled enc = (PFN_encodeTiled)fn;

    void *pXhi, *pXlo, *pW8;
    cudaGetSymbolAddress(&pXhi, g_Xhi);
    cudaGetSymbolAddress(&pXlo, g_Xlo);
    cudaGetSymbolAddress(&pW8,  g_W8);

    CUtensorMap tmXhi, tmXlo, tmB;
    make_map2d(enc, &tmXhi, pXhi, Kdim, Mdim, KC, 128);
    make_map2d(enc, &tmXlo, pXlo, Kdim, Mdim, KC, 128);
    make_map2d(enc, &tmB,   pW8,  Kdim, Ndim, KC, 128);

    cudaFuncSetAttribute((const void*)gemm_kernel,
                         cudaFuncAttributeMaxDynamicSharedMemorySize, SMEM_TOTAL);

    int nW4 = (Ndim * Kdim) / 4;
    int nX4 = (Mdim * Kdim) / 4;

    k_init<<<1, 32>>>();
    k_absmax<<<512, 256>>>((const float4*)W, nW4);
    k_quant<<<2048, 256>>>((const float4*)W, nW4);
    k_split<<<4096, 256>>>((const float4*)x, nX4);
    gemm_kernel<<<NPAIRS * 2, 192, SMEM_TOTAL>>>(tmXhi, tmXlo, tmB, b, out);
    // no-op (per-block early exit) when the tcgen05 image is loaded
    fallback_gemm<<<dim3(Ndim / 64, Mdim / 64), 256>>>(x, b, out);
}